// round 13
// baseline (speedup 1.0000x reference)
#include <cuda_runtime.h>
#include <cuda_bf16.h>
#include <stdint.h>
#include <stddef.h>
#include <math.h>

#define BATCH 4
#define T     2048
#define D     1024
#define MT    (BATCH * T)   // 8192

// CTA tile 128x128, 8 warps (2M x 4N), warp tile 64x32, base-K chunk = 16
#define TM 128
#define TN 128
#define BKB 16
// A/B (mode!=2) tiles: plane-split layout, 2 planes x 128 rows x 16B, plane1
// rotated by 64B -> conflict-free STS.128 AND conflict-free ldsm. 4096B/tile.
#define B2STR 136    // mode2 V tiles: 128+8 pad elems (272B rows), conflict-free

// ------------------------- device scratch (hi/lo pairs) --------------------
__device__ __nv_bfloat16 g_Eh[(size_t)MT * D],  g_El[(size_t)MT * D];
__device__ __nv_bfloat16 g_WTh[(size_t)3 * D * D], g_WTl[(size_t)3 * D * D]; // [z][n][k]
__device__ __nv_bfloat16 g_Qh[(size_t)MT * D],  g_Ql[(size_t)MT * D];
__device__ __nv_bfloat16 g_Kh[(size_t)MT * D],  g_Kl[(size_t)MT * D];
__device__ __nv_bfloat16 g_Vh[(size_t)MT * D],  g_Vl[(size_t)MT * D];       // [b][t][d]
__device__ float         g_S[(size_t)BATCH * T * T];                         // fp32 scores
__device__ __nv_bfloat16 g_Sh[(size_t)BATCH * T * T], g_Sl[(size_t)BATCH * T * T];

// ------------------------- helpers ------------------------------------
__device__ __forceinline__ uint32_t smem_u32(const void* p) {
    uint32_t a;
    asm("{ .reg .u64 t; cvta.to.shared.u64 t, %1; cvt.u32.u64 %0, t; }" : "=r"(a) : "l"(p));
    return a;
}
// byte offset of (row, k-half) 16B chunk inside a plane-split tile
__device__ __forceinline__ int pOff(int row, int half) {
    return half * 2048 + (((row << 4) + (half << 6)) & 2047);
}
__device__ __forceinline__ void ldsm_x4(uint32_t& r0, uint32_t& r1, uint32_t& r2, uint32_t& r3,
                                        uint32_t addr) {
    asm volatile("ldmatrix.sync.aligned.m8n8.x4.shared.b16 {%0,%1,%2,%3}, [%4];"
                 : "=r"(r0), "=r"(r1), "=r"(r2), "=r"(r3) : "r"(addr));
}
__device__ __forceinline__ void ldsm_x4_t(uint32_t& r0, uint32_t& r1, uint32_t& r2, uint32_t& r3,
                                          uint32_t addr) {
    asm volatile("ldmatrix.sync.aligned.m8n8.x4.trans.shared.b16 {%0,%1,%2,%3}, [%4];"
                 : "=r"(r0), "=r"(r1), "=r"(r2), "=r"(r3) : "r"(addr));
}
__device__ __forceinline__ void mma_bf16(float* c, const uint32_t* a, const uint32_t* b) {
    asm volatile("mma.sync.aligned.m16n8k16.row.col.f32.bf16.bf16.f32 "
                 "{%0,%1,%2,%3}, {%4,%5,%6,%7}, {%8,%9}, {%0,%1,%2,%3};"
                 : "+f"(c[0]), "+f"(c[1]), "+f"(c[2]), "+f"(c[3])
                 : "r"(a[0]), "r"(a[1]), "r"(a[2]), "r"(a[3]), "r"(b[0]), "r"(b[1]));
}
__device__ __forceinline__ void bsplit(float x, __nv_bfloat16& h, __nv_bfloat16& l) {
    h = __float2bfloat16(x);
    l = __float2bfloat16(x - __bfloat162float(h));
}
__device__ __forceinline__ __nv_bfloat162 mk2(__nv_bfloat16 a, __nv_bfloat16 b) {
    __nv_bfloat162 v; v.x = a; v.y = b; return v;
}

// ------------------------- conversion kernels ------------------------------
__global__ __launch_bounds__(256)
void convE_kernel(const float* __restrict__ E) {
    int idx = blockIdx.x * 256 + threadIdx.x;   // over MT*D
    __nv_bfloat16 h, l;
    bsplit(E[idx], h, l);
    g_Eh[idx] = h; g_El[idx] = l;
}

__global__ __launch_bounds__(256)
void convW_kernel(const float* __restrict__ Wk, const float* __restrict__ Wq,
                  const float* __restrict__ Wv) {
    const float* W = (blockIdx.z == 0) ? Wk : (blockIdx.z == 1) ? Wq : Wv;
    const size_t zoff = (size_t)blockIdx.z * D * D;
    __shared__ float tsm[32][33];
    int n0 = blockIdx.x * 32, k0 = blockIdx.y * 32;
    int tx = threadIdx.x, ty = threadIdx.y;
    #pragma unroll
    for (int i = 0; i < 4; i++)
        tsm[ty + 8 * i][tx] = W[(size_t)(k0 + ty + 8 * i) * D + n0 + tx];
    __syncthreads();
    #pragma unroll
    for (int i = 0; i < 4; i++) {
        int n = n0 + ty + 8 * i, k = k0 + tx;
        __nv_bfloat16 h, l;
        bsplit(tsm[tx][ty + 8 * i], h, l);       // = W[k][n]
        g_WTh[zoff + (size_t)n * D + k] = h;     // [n][k]
        g_WTl[zoff + (size_t)n * D + k] = l;
    }
}

// ------------------------- unified mma.sync GEMM ---------------------------
// 3-pass split-bf16, chained operand reuse:
//   pass1 Al*Bh  -> pass2 Ah*Bh (B held) -> pass3 Ah*Bl (A held)
// Every tile ldsm'd exactly once: 12 ldsm.x4 / iter (was 14).
// MODE 0: qkv   out = E @ WT[z]^T                 grid (8, 64, 3), K=1024
// MODE 1: score S[b] = Q @ K^T (/32, causal)      grid (16, 16, 4), K=1024
// MODE 2: av    O[b] = S @ V (trans-B, bounded)   grid (8, 16, 4),  K<=2048
template <int MODE>
__global__ __launch_bounds__(256, 2)
void gemm_mma(float* __restrict__ outp) {
    // A tiles: 2048 elems (4096B, plane-split). B tiles: 2304 elems
    // (mode!=2 uses first 2048 plane-split; mode2 uses 16*B2STR=2176 padded).
    __shared__ __align__(128) __nv_bfloat16 sAh[2][2048], sAl[2][2048];
    __shared__ __align__(128) __nv_bfloat16 sBh[2][2304], sBl[2][2304];

    const int tid = threadIdx.x;
    const int wid = tid >> 5, l = tid & 31;
    const int wm = wid & 1, wn = wid >> 1;          // 2(M) x 4(N) warp grid
    const int warpM = wm * 64, warpN = wn * 32;     // warp tile 64x32
    const int bx = blockIdx.x, by = blockIdx.y, bz = blockIdx.z;
    const int mBase = by * TM, nBase = bx * TN;

    const __nv_bfloat16 *Agh, *Agl, *Bgh, *Bgl;
    int ldkA, nIter;
    if (MODE == 0) {
        Agh = g_Eh; Agl = g_El;
        Bgh = g_WTh + (size_t)bz * D * D; Bgl = g_WTl + (size_t)bz * D * D;
        ldkA = D; nIter = D / BKB;
    } else if (MODE == 1) {
        if (bx > by) return;                        // strictly above diagonal
        Agh = g_Qh + (size_t)bz * T * D; Agl = g_Ql + (size_t)bz * T * D;
        Bgh = g_Kh + (size_t)bz * T * D; Bgl = g_Kl + (size_t)bz * T * D;
        ldkA = D; nIter = D / BKB;
    } else {
        Agh = g_Sh + (size_t)bz * T * T; Agl = g_Sl + (size_t)bz * T * T;
        Bgh = g_Vh + (size_t)bz * T * D; Bgl = g_Vl + (size_t)bz * T * D;
        ldkA = T; nIter = ((by + 1) * TM) / BKB;    // causal K bound
    }

    float c[4][4][4] = {};
    uint4 pt[4];

    // ---- global loader (into registers); one 16B chunk per thread per tile ----
    const int aRow = tid >> 1;
    const int aHalf = tid & 1;
    const int aSts = pOff(aRow, aHalf);        // plane-split STS offset (bytes)
    const int vRow = tid >> 4;                 // mode2 B tile rows
    const int vNc  = (tid & 15) * 8;

    auto loadG = [&](int ko) {
        const size_t aoff = (size_t)(mBase + aRow) * ldkA + ko + aHalf * 8;
        pt[0] = *(const uint4*)(Agh + aoff);
        pt[1] = *(const uint4*)(Agl + aoff);
        if (MODE != 2) {
            const size_t boff = (size_t)(nBase + aRow) * D + ko + aHalf * 8;
            pt[2] = *(const uint4*)(Bgh + boff);
            pt[3] = *(const uint4*)(Bgl + boff);
        } else {
            const size_t boff = (size_t)(ko + vRow) * D + nBase + vNc;
            pt[2] = *(const uint4*)(Bgh + boff);
            pt[3] = *(const uint4*)(Bgl + boff);
        }
    };
    auto stsAll = [&](int buf) {
        *(uint4*)((char*)sAh[buf] + aSts) = pt[0];
        *(uint4*)((char*)sAl[buf] + aSts) = pt[1];
        if (MODE != 2) {
            *(uint4*)((char*)sBh[buf] + aSts) = pt[2];
            *(uint4*)((char*)sBl[buf] + aSts) = pt[3];
        } else {
            *(uint4*)&sBh[buf][vRow * B2STR + vNc] = pt[2];
            *(uint4*)&sBl[buf][vRow * B2STR + vNc] = pt[3];
        }
    };

    // lane-invariant ldsm addressing pieces (plane-split layout)
    const int aPl = l >> 4;                         // A: plane select
    const int aRw = ((l >> 3) & 1) * 8 + (l & 7);   // A: row within 16-group
    const int bPl = (l >> 3) & 1;                   // B: plane select
    const int bRw = (l & 7) + (l >> 4) * 8;         // B: row within 16-group
    // mode2 trans ldsm pieces (padded [k][n] layout)
    const int vLR = ((l >> 3) & 1) * 8 + (l & 7), vLC = (l >> 4) * 8;

    auto ldsmA = [&](uint32_t (&a)[4][4], const __nv_bfloat16* base) {
        const uint32_t u = smem_u32(base);
        #pragma unroll
        for (int mi = 0; mi < 4; mi++)
            ldsm_x4(a[mi][0], a[mi][1], a[mi][2], a[mi][3],
                    u + pOff(warpM + mi * 16 + aRw, aPl));
    };
    auto ldsmB = [&](uint32_t (&b)[4][2], const __nv_bfloat16* base) {
        const uint32_t u = smem_u32(base);
        if (MODE != 2) {
            #pragma unroll
            for (int n2 = 0; n2 < 4; n2 += 2)
                ldsm_x4(b[n2][0], b[n2][1], b[n2 + 1][0], b[n2 + 1][1],
                        u + pOff(warpN + n2 * 8 + bRw, bPl));
        } else {
            #pragma unroll
            for (int n2 = 0; n2 < 4; n2 += 2)
                ldsm_x4_t(b[n2][0], b[n2][1], b[n2 + 1][0], b[n2 + 1][1],
                          u + (vLR * B2STR + warpN + n2 * 8 + vLC) * 2);
        }
    };
    auto mmaAll = [&](uint32_t (&a)[4][4], uint32_t (&b)[4][2]) {
        #pragma unroll
        for (int mi = 0; mi < 4; mi++)
            #pragma unroll
            for (int ni = 0; ni < 4; ni++)
                mma_bf16(c[mi][ni], a[mi], b[ni]);
    };

    // ---- prologue: fill buffer 0 ----
    loadG(0);
    stsAll(0);
    __syncthreads();

    // ---- main loop: one barrier per iteration, chained 3-pass ----
    for (int it = 0; it < nIter; it++) {
        const int buf = it & 1;
        const bool more = (it + 1 < nIter);
        if (more) loadG((it + 1) * BKB);   // LDG latency rides under the MMAs

        uint32_t a[4][4], b[4][2];
        ldsmA(a, sAl[buf]);
        ldsmB(b, sBh[buf]);
        mmaAll(a, b);                      // Al * Bh
        ldsmA(a, sAh[buf]);
        mmaAll(a, b);                      // Ah * Bh   (b held in regs)

        if (more) stsAll(buf ^ 1);         // STS drains under pass 3's MMAs

        ldsmB(b, sBl[buf]);
        mmaAll(a, b);                      // Ah * Bl   (a held in regs)

        if (more) __syncthreads();         // single barrier per iteration
    }

    // ---- epilogue (direct from accumulators) ----
    const int l4 = l >> 2, l2 = (l & 3) * 2;
    #pragma unroll
    for (int mi = 0; mi < 4; mi++) {
        #pragma unroll
        for (int ni = 0; ni < 4; ni++) {
            const int n = nBase + warpN + ni * 8 + l2;
            #pragma unroll
            for (int half = 0; half < 2; half++) {
                const int m = mBase + warpM + mi * 16 + l4 + half * 8;
                float v0 = c[mi][ni][half * 2 + 0];
                float v1 = c[mi][ni][half * 2 + 1];
                if (MODE == 0) {
                    __nv_bfloat16 h0, l0, h1, l1;
                    bsplit(v0, h0, l0); bsplit(v1, h1, l1);
                    const size_t off = (size_t)m * D + n;
                    if (bz == 1) {
                        *(__nv_bfloat162*)(g_Qh + off) = mk2(h0, h1);
                        *(__nv_bfloat162*)(g_Ql + off) = mk2(l0, l1);
                    } else if (bz == 0) {
                        *(__nv_bfloat162*)(g_Kh + off) = mk2(h0, h1);
                        *(__nv_bfloat162*)(g_Kl + off) = mk2(l0, l1);
                    } else {
                        *(__nv_bfloat162*)(g_Vh + off) = mk2(h0, h1);   // [b][t][d]
                        *(__nv_bfloat162*)(g_Vl + off) = mk2(l0, l1);
                    }
                } else if (MODE == 1) {
                    float s0 = (n     > m) ? -INFINITY : v0 * 0.03125f;
                    float s1 = (n + 1 > m) ? -INFINITY : v1 * 0.03125f;
                    float* p = g_S + (size_t)bz * T * T + (size_t)m * T + n;
                    p[0] = s0; p[1] = s1;
                } else {
                    float* p = outp + (size_t)bz * T * D + (size_t)m * D + n;
                    p[0] = rintf(v0 * 10000.0f) * 1.0e-4f;
                    p[1] = rintf(v1 * 10000.0f) * 1.0e-4f;
                }
            }
        }
    }
}

// ------------------------- softmax (warp per row) -> split bf16 ------------
__global__ __launch_bounds__(256)
void softmax_kernel() {
    const int wid = threadIdx.x >> 5, l = threadIdx.x & 31;
    const int r = blockIdx.x * 8 + wid;
    const int b = r >> 11, t = r & (T - 1);
    float* row = g_S + (size_t)b * T * T + (size_t)t * T;
    __nv_bfloat16* oh = g_Sh + ((size_t)b * T + t) * T;
    __nv_bfloat16* ol = g_Sl + ((size_t)b * T + t) * T;
    const int L = ((t >> 7) + 1) << 7;   // ceil to 128-tile

    float m = -INFINITY;
    for (int j = l; j < L; j += 32) m = fmaxf(m, row[j]);
    #pragma unroll
    for (int off = 16; off > 0; off >>= 1)
        m = fmaxf(m, __shfl_xor_sync(0xFFFFFFFFu, m, off));

    float sum = 0.0f;
    for (int j = l; j < L; j += 32) {
        float e = __expf(row[j] - m);   // exp(-inf)=0 handles the causal mask
        row[j] = e;
        sum += e;
    }
    #pragma unroll
    for (int off = 16; off > 0; off >>= 1)
        sum += __shfl_xor_sync(0xFFFFFFFFu, sum, off);
    const float inv = 1.0f / sum;

    for (int j = l; j < L; j += 32) {
        float w = row[j] * inv;
        __nv_bfloat16 h, ll;
        bsplit(w, h, ll);
        oh[j] = h; ol[j] = ll;
    }
}

// ---------------------------------------------------------------------------
extern "C" void kernel_launch(void* const* d_in, const int* in_sizes, int n_in,
                              void* d_out, int out_size) {
    const float* E  = (const float*)d_in[0];
    const float* Wk = (const float*)d_in[1];
    const float* Wq = (const float*)d_in[2];
    const float* Wv = (const float*)d_in[3];
    float* O = (float*)d_out;

    convE_kernel<<<(MT * D) / 256, 256>>>(E);
    convW_kernel<<<dim3(32, 32, 3), dim3(32, 8)>>>(Wk, Wq, Wv);
    gemm_mma<0><<<dim3(D / TN, MT / TM, 3), 256>>>(O);
    gemm_mma<1><<<dim3(T / TN, T / TM, BATCH), 256>>>(O);
    softmax_kernel<<<MT / 8, 256>>>();
    gemm_mma<2><<<dim3(D / TN, T / TM, BATCH), 256>>>(O);
}

// round 14
// speedup vs baseline: 1.0991x; 1.0991x over previous
#include <cuda_runtime.h>
#include <cuda_bf16.h>
#include <stdint.h>
#include <stddef.h>
#include <math.h>

#define BATCH 4
#define T     2048
#define D     1024
#define MT    (BATCH * T)   // 8192

// CTA tile 128x128, 8 warps (2M x 4N), warp tile 64x32, base-K chunk = 16
#define TM 128
#define TN 128
#define BKB 16
// A/B (mode!=2) tiles: plane-split layout, 2 planes x 128 rows x 16B, plane1
// rotated by 64B -> conflict-free STS.128 AND conflict-free ldsm. 4096B/tile.
#define B2STR 136    // mode2 V tiles: 128+8 pad elems (272B rows), conflict-free

// ------------------------- device scratch (hi/lo pairs) --------------------
__device__ __nv_bfloat16 g_Eh[(size_t)MT * D],  g_El[(size_t)MT * D];
__device__ __nv_bfloat16 g_WTh[(size_t)3 * D * D], g_WTl[(size_t)3 * D * D]; // [z][n][k]
__device__ __nv_bfloat16 g_Qh[(size_t)MT * D],  g_Ql[(size_t)MT * D];
__device__ __nv_bfloat16 g_Kh[(size_t)MT * D],  g_Kl[(size_t)MT * D];
__device__ __nv_bfloat16 g_Vh[(size_t)MT * D],  g_Vl[(size_t)MT * D];       // [b][t][d]
__device__ float         g_S[(size_t)BATCH * T * T];                         // fp32 scores
__device__ __nv_bfloat16 g_Sh[(size_t)BATCH * T * T], g_Sl[(size_t)BATCH * T * T];

// ------------------------- helpers ------------------------------------
__device__ __forceinline__ uint32_t smem_u32(const void* p) {
    uint32_t a;
    asm("{ .reg .u64 t; cvta.to.shared.u64 t, %1; cvt.u32.u64 %0, t; }" : "=r"(a) : "l"(p));
    return a;
}
// byte offset of (row, k-half) 16B chunk inside a plane-split tile
__device__ __forceinline__ int pOff(int row, int half) {
    return half * 2048 + (((row << 4) + (half << 6)) & 2047);
}
__device__ __forceinline__ void ldsm_x4(uint32_t& r0, uint32_t& r1, uint32_t& r2, uint32_t& r3,
                                        uint32_t addr) {
    asm volatile("ldmatrix.sync.aligned.m8n8.x4.shared.b16 {%0,%1,%2,%3}, [%4];"
                 : "=r"(r0), "=r"(r1), "=r"(r2), "=r"(r3) : "r"(addr));
}
__device__ __forceinline__ void ldsm_x4_t(uint32_t& r0, uint32_t& r1, uint32_t& r2, uint32_t& r3,
                                          uint32_t addr) {
    asm volatile("ldmatrix.sync.aligned.m8n8.x4.trans.shared.b16 {%0,%1,%2,%3}, [%4];"
                 : "=r"(r0), "=r"(r1), "=r"(r2), "=r"(r3) : "r"(addr));
}
__device__ __forceinline__ void mma_bf16(float* c, const uint32_t* a, const uint32_t* b) {
    asm volatile("mma.sync.aligned.m16n8k16.row.col.f32.bf16.bf16.f32 "
                 "{%0,%1,%2,%3}, {%4,%5,%6,%7}, {%8,%9}, {%0,%1,%2,%3};"
                 : "+f"(c[0]), "+f"(c[1]), "+f"(c[2]), "+f"(c[3])
                 : "r"(a[0]), "r"(a[1]), "r"(a[2]), "r"(a[3]), "r"(b[0]), "r"(b[1]));
}
__device__ __forceinline__ void bsplit(float x, __nv_bfloat16& h, __nv_bfloat16& l) {
    h = __float2bfloat16(x);
    l = __float2bfloat16(x - __bfloat162float(h));
}
__device__ __forceinline__ __nv_bfloat162 mk2(__nv_bfloat16 a, __nv_bfloat16 b) {
    __nv_bfloat162 v; v.x = a; v.y = b; return v;
}

// ------------------------- conversion kernels ------------------------------
__global__ __launch_bounds__(256)
void convE_kernel(const float* __restrict__ E) {
    int idx = blockIdx.x * 256 + threadIdx.x;   // over MT*D
    __nv_bfloat16 h, l;
    bsplit(E[idx], h, l);
    g_Eh[idx] = h; g_El[idx] = l;
}

__global__ __launch_bounds__(256)
void convW_kernel(const float* __restrict__ Wk, const float* __restrict__ Wq,
                  const float* __restrict__ Wv) {
    const float* W = (blockIdx.z == 0) ? Wk : (blockIdx.z == 1) ? Wq : Wv;
    const size_t zoff = (size_t)blockIdx.z * D * D;
    __shared__ float tsm[32][33];
    int n0 = blockIdx.x * 32, k0 = blockIdx.y * 32;
    int tx = threadIdx.x, ty = threadIdx.y;
    #pragma unroll
    for (int i = 0; i < 4; i++)
        tsm[ty + 8 * i][tx] = W[(size_t)(k0 + ty + 8 * i) * D + n0 + tx];
    __syncthreads();
    #pragma unroll
    for (int i = 0; i < 4; i++) {
        int n = n0 + ty + 8 * i, k = k0 + tx;
        __nv_bfloat16 h, l;
        bsplit(tsm[tx][ty + 8 * i], h, l);       // = W[k][n]
        g_WTh[zoff + (size_t)n * D + k] = h;     // [n][k]
        g_WTl[zoff + (size_t)n * D + k] = l;
    }
}

// ------------------------- unified mma.sync GEMM ---------------------------
// 3-pass split-bf16, chained operand reuse (each tile ldsm'd exactly once):
//   pass1 Al*Bh -> pass2 Ah*Bh (B held) -> pass3 Ah*Bl (A held)
// STS + barrier at END of iteration (R12 placement — mid-loop STS regressed).
// MODE 0: qkv   out = E @ WT[z]^T                 grid (8, 64, 3), K=1024
// MODE 1: score S[b] = Q @ K^T (/32, causal)      grid (16, 16, 4), K=1024
// MODE 2: av    O[b] = S @ V (trans-B, bounded)   grid (8, 16, 4),  K<=2048
template <int MODE>
__global__ __launch_bounds__(256, 2)
void gemm_mma(float* __restrict__ outp) {
    // A tiles: 2048 elems (4096B, plane-split). B tiles: 2304 elems
    // (mode!=2 uses first 2048 plane-split; mode2 uses 16*B2STR=2176 padded).
    __shared__ __align__(128) __nv_bfloat16 sAh[2][2048], sAl[2][2048];
    __shared__ __align__(128) __nv_bfloat16 sBh[2][2304], sBl[2][2304];

    const int tid = threadIdx.x;
    const int wid = tid >> 5, l = tid & 31;
    const int wm = wid & 1, wn = wid >> 1;          // 2(M) x 4(N) warp grid
    const int warpM = wm * 64, warpN = wn * 32;     // warp tile 64x32
    const int bx = blockIdx.x, by = blockIdx.y, bz = blockIdx.z;
    const int mBase = by * TM, nBase = bx * TN;

    const __nv_bfloat16 *Agh, *Agl, *Bgh, *Bgl;
    int ldkA, nIter;
    if (MODE == 0) {
        Agh = g_Eh; Agl = g_El;
        Bgh = g_WTh + (size_t)bz * D * D; Bgl = g_WTl + (size_t)bz * D * D;
        ldkA = D; nIter = D / BKB;
    } else if (MODE == 1) {
        if (bx > by) return;                        // strictly above diagonal
        Agh = g_Qh + (size_t)bz * T * D; Agl = g_Ql + (size_t)bz * T * D;
        Bgh = g_Kh + (size_t)bz * T * D; Bgl = g_Kl + (size_t)bz * T * D;
        ldkA = D; nIter = D / BKB;
    } else {
        Agh = g_Sh + (size_t)bz * T * T; Agl = g_Sl + (size_t)bz * T * T;
        Bgh = g_Vh + (size_t)bz * T * D; Bgl = g_Vl + (size_t)bz * T * D;
        ldkA = T; nIter = ((by + 1) * TM) / BKB;    // causal K bound
    }

    float c[4][4][4] = {};
    uint4 pt[4];

    // ---- global loader (into registers); one 16B chunk per thread per tile ----
    const int aRow = tid >> 1;
    const int aHalf = tid & 1;
    const int aSts = pOff(aRow, aHalf);        // plane-split STS offset (bytes)
    const int vRow = tid >> 4;                 // mode2 B tile rows
    const int vNc  = (tid & 15) * 8;

    auto loadG = [&](int ko) {
        const size_t aoff = (size_t)(mBase + aRow) * ldkA + ko + aHalf * 8;
        pt[0] = *(const uint4*)(Agh + aoff);
        pt[1] = *(const uint4*)(Agl + aoff);
        if (MODE != 2) {
            const size_t boff = (size_t)(nBase + aRow) * D + ko + aHalf * 8;
            pt[2] = *(const uint4*)(Bgh + boff);
            pt[3] = *(const uint4*)(Bgl + boff);
        } else {
            const size_t boff = (size_t)(ko + vRow) * D + nBase + vNc;
            pt[2] = *(const uint4*)(Bgh + boff);
            pt[3] = *(const uint4*)(Bgl + boff);
        }
    };
    auto stsAll = [&](int buf) {
        *(uint4*)((char*)sAh[buf] + aSts) = pt[0];
        *(uint4*)((char*)sAl[buf] + aSts) = pt[1];
        if (MODE != 2) {
            *(uint4*)((char*)sBh[buf] + aSts) = pt[2];
            *(uint4*)((char*)sBl[buf] + aSts) = pt[3];
        } else {
            *(uint4*)&sBh[buf][vRow * B2STR + vNc] = pt[2];
            *(uint4*)&sBl[buf][vRow * B2STR + vNc] = pt[3];
        }
    };

    // lane-invariant ldsm addressing pieces (plane-split layout)
    const int aPl = l >> 4;                         // A: plane select
    const int aRw = ((l >> 3) & 1) * 8 + (l & 7);   // A: row within 16-group
    const int bPl = (l >> 3) & 1;                   // B: plane select
    const int bRw = (l & 7) + (l >> 4) * 8;         // B: row within 16-group
    // mode2 trans ldsm pieces (padded [k][n] layout)
    const int vLR = ((l >> 3) & 1) * 8 + (l & 7), vLC = (l >> 4) * 8;

    auto ldsmA = [&](uint32_t (&a)[4][4], const __nv_bfloat16* base) {
        const uint32_t u = smem_u32(base);
        #pragma unroll
        for (int mi = 0; mi < 4; mi++)
            ldsm_x4(a[mi][0], a[mi][1], a[mi][2], a[mi][3],
                    u + pOff(warpM + mi * 16 + aRw, aPl));
    };
    auto ldsmB = [&](uint32_t (&b)[4][2], const __nv_bfloat16* base) {
        const uint32_t u = smem_u32(base);
        if (MODE != 2) {
            #pragma unroll
            for (int n2 = 0; n2 < 4; n2 += 2)
                ldsm_x4(b[n2][0], b[n2][1], b[n2 + 1][0], b[n2 + 1][1],
                        u + pOff(warpN + n2 * 8 + bRw, bPl));
        } else {
            #pragma unroll
            for (int n2 = 0; n2 < 4; n2 += 2)
                ldsm_x4_t(b[n2][0], b[n2][1], b[n2 + 1][0], b[n2 + 1][1],
                          u + (vLR * B2STR + warpN + n2 * 8 + vLC) * 2);
        }
    };
    auto mmaAll = [&](uint32_t (&a)[4][4], uint32_t (&b)[4][2]) {
        #pragma unroll
        for (int mi = 0; mi < 4; mi++)
            #pragma unroll
            for (int ni = 0; ni < 4; ni++)
                mma_bf16(c[mi][ni], a[mi], b[ni]);
    };

    // ---- prologue: fill buffer 0 ----
    loadG(0);
    stsAll(0);
    __syncthreads();

    // ---- main loop: one barrier per iter, 12 ldsm, STS at end (R12 style) ----
    for (int it = 0; it < nIter; it++) {
        const int buf = it & 1;
        const bool more = (it + 1 < nIter);
        if (more) loadG((it + 1) * BKB);   // LDG latency rides under the MMAs

        uint32_t a[4][4], b[4][2];
        ldsmA(a, sAl[buf]);
        ldsmB(b, sBh[buf]);
        mmaAll(a, b);                      // Al * Bh
        ldsmA(a, sAh[buf]);
        mmaAll(a, b);                      // Ah * Bh   (b held in regs)
        ldsmB(b, sBl[buf]);
        mmaAll(a, b);                      // Ah * Bl   (a held in regs)

        if (more) {
            stsAll(buf ^ 1);               // other buffer; safe before barrier
            __syncthreads();               // single barrier per iteration
        }
    }

    // ---- epilogue (direct from accumulators) ----
    const int l4 = l >> 2, l2 = (l & 3) * 2;
    #pragma unroll
    for (int mi = 0; mi < 4; mi++) {
        #pragma unroll
        for (int ni = 0; ni < 4; ni++) {
            const int n = nBase + warpN + ni * 8 + l2;
            #pragma unroll
            for (int half = 0; half < 2; half++) {
                const int m = mBase + warpM + mi * 16 + l4 + half * 8;
                float v0 = c[mi][ni][half * 2 + 0];
                float v1 = c[mi][ni][half * 2 + 1];
                if (MODE == 0) {
                    __nv_bfloat16 h0, l0, h1, l1;
                    bsplit(v0, h0, l0); bsplit(v1, h1, l1);
                    const size_t off = (size_t)m * D + n;
                    if (bz == 1) {
                        *(__nv_bfloat162*)(g_Qh + off) = mk2(h0, h1);
                        *(__nv_bfloat162*)(g_Ql + off) = mk2(l0, l1);
                    } else if (bz == 0) {
                        *(__nv_bfloat162*)(g_Kh + off) = mk2(h0, h1);
                        *(__nv_bfloat162*)(g_Kl + off) = mk2(l0, l1);
                    } else {
                        *(__nv_bfloat162*)(g_Vh + off) = mk2(h0, h1);   // [b][t][d]
                        *(__nv_bfloat162*)(g_Vl + off) = mk2(l0, l1);
                    }
                } else if (MODE == 1) {
                    float s0 = (n     > m) ? -INFINITY : v0 * 0.03125f;
                    float s1 = (n + 1 > m) ? -INFINITY : v1 * 0.03125f;
                    float* p = g_S + (size_t)bz * T * T + (size_t)m * T + n;
                    p[0] = s0; p[1] = s1;
                } else {
                    float* p = outp + (size_t)bz * T * D + (size_t)m * D + n;
                    p[0] = rintf(v0 * 10000.0f) * 1.0e-4f;
                    p[1] = rintf(v1 * 10000.0f) * 1.0e-4f;
                }
            }
        }
    }
}

// ------------------------- softmax (warp per row) -> split bf16 ------------
__global__ __launch_bounds__(256)
void softmax_kernel() {
    const int wid = threadIdx.x >> 5, l = threadIdx.x & 31;
    const int r = blockIdx.x * 8 + wid;
    const int b = r >> 11, t = r & (T - 1);
    float* row = g_S + (size_t)b * T * T + (size_t)t * T;
    __nv_bfloat16* oh = g_Sh + ((size_t)b * T + t) * T;
    __nv_bfloat16* ol = g_Sl + ((size_t)b * T + t) * T;
    const int L = ((t >> 7) + 1) << 7;   // ceil to 128-tile

    float m = -INFINITY;
    for (int j = l; j < L; j += 32) m = fmaxf(m, row[j]);
    #pragma unroll
    for (int off = 16; off > 0; off >>= 1)
        m = fmaxf(m, __shfl_xor_sync(0xFFFFFFFFu, m, off));

    float sum = 0.0f;
    for (int j = l; j < L; j += 32) {
        float e = __expf(row[j] - m);   // exp(-inf)=0 handles the causal mask
        row[j] = e;
        sum += e;
    }
    #pragma unroll
    for (int off = 16; off > 0; off >>= 1)
        sum += __shfl_xor_sync(0xFFFFFFFFu, sum, off);
    const float inv = 1.0f / sum;

    for (int j = l; j < L; j += 32) {
        float w = row[j] * inv;
        __nv_bfloat16 h, ll;
        bsplit(w, h, ll);
        oh[j] = h; ol[j] = ll;
    }
}

// ---------------------------------------------------------------------------
extern "C" void kernel_launch(void* const* d_in, const int* in_sizes, int n_in,
                              void* d_out, int out_size) {
    const float* E  = (const float*)d_in[0];
    const float* Wk = (const float*)d_in[1];
    const float* Wq = (const float*)d_in[2];
    const float* Wv = (const float*)d_in[3];
    float* O = (float*)d_out;

    convE_kernel<<<(MT * D) / 256, 256>>>(E);
    convW_kernel<<<dim3(32, 32, 3), dim3(32, 8)>>>(Wk, Wq, Wv);
    gemm_mma<0><<<dim3(D / TN, MT / TM, 3), 256>>>(O);
    gemm_mma<1><<<dim3(T / TN, T / TM, BATCH), 256>>>(O);
    softmax_kernel<<<MT / 8, 256>>>();
    gemm_mma<2><<<dim3(D / TN, T / TM, BATCH), 256>>>(O);
}

// round 15
// speedup vs baseline: 1.2075x; 1.0987x over previous
#include <cuda_runtime.h>
#include <cuda_bf16.h>
#include <cuda_fp16.h>
#include <stdint.h>
#include <stddef.h>
#include <math.h>

#define BATCH 4
#define T     2048
#define D     1024
#define MT    (BATCH * T)   // 8192

// CTA tile 128x128, 8 warps (2M x 4N), warp tile 64x32, base-K chunk = 16
#define TM 128
#define TN 128
#define BKB 16
// A/B (mode!=2) tiles: plane-split layout, 2 planes x 128 rows x 16B, plane1
// rotated by 64B -> conflict-free STS.128 AND conflict-free ldsm. 4096B/tile.
#define B2STR 136    // mode2 V tiles: 128+8 pad elems (272B rows), conflict-free

// ------------------------- device scratch --------------------------------
// E, W: bf16 hi/lo (QKV projection stays 3-pass bf16 for accurate intermediates)
__device__ __nv_bfloat16 g_Eh[(size_t)MT * D],  g_El[(size_t)MT * D];
__device__ __nv_bfloat16 g_WTh[(size_t)3 * D * D], g_WTl[(size_t)3 * D * D]; // [z][n][k]
// Q: fp16 hi/lo (split side of scores). K, V: single fp16.
__device__ __half g_Qh[(size_t)MT * D], g_Ql[(size_t)MT * D];
__device__ __half g_Kh[(size_t)MT * D];
__device__ __half g_Vh[(size_t)MT * D];                     // [b][t][d]
__device__ float  g_S[(size_t)BATCH * T * T];               // fp32 scores
__device__ __half g_Sh[(size_t)BATCH * T * T], g_Sl[(size_t)BATCH * T * T];

// ------------------------- helpers ------------------------------------
__device__ __forceinline__ uint32_t smem_u32(const void* p) {
    uint32_t a;
    asm("{ .reg .u64 t; cvta.to.shared.u64 t, %1; cvt.u32.u64 %0, t; }" : "=r"(a) : "l"(p));
    return a;
}
// byte offset of (row, k-half) 16B chunk inside a plane-split tile
__device__ __forceinline__ int pOff(int row, int half) {
    return half * 2048 + (((row << 4) + (half << 6)) & 2047);
}
__device__ __forceinline__ void ldsm_x4(uint32_t& r0, uint32_t& r1, uint32_t& r2, uint32_t& r3,
                                        uint32_t addr) {
    asm volatile("ldmatrix.sync.aligned.m8n8.x4.shared.b16 {%0,%1,%2,%3}, [%4];"
                 : "=r"(r0), "=r"(r1), "=r"(r2), "=r"(r3) : "r"(addr));
}
__device__ __forceinline__ void ldsm_x4_t(uint32_t& r0, uint32_t& r1, uint32_t& r2, uint32_t& r3,
                                          uint32_t addr) {
    asm volatile("ldmatrix.sync.aligned.m8n8.x4.trans.shared.b16 {%0,%1,%2,%3}, [%4];"
                 : "=r"(r0), "=r"(r1), "=r"(r2), "=r"(r3) : "r"(addr));
}
__device__ __forceinline__ void mma_bf16(float* c, const uint32_t* a, const uint32_t* b) {
    asm volatile("mma.sync.aligned.m16n8k16.row.col.f32.bf16.bf16.f32 "
                 "{%0,%1,%2,%3}, {%4,%5,%6,%7}, {%8,%9}, {%0,%1,%2,%3};"
                 : "+f"(c[0]), "+f"(c[1]), "+f"(c[2]), "+f"(c[3])
                 : "r"(a[0]), "r"(a[1]), "r"(a[2]), "r"(a[3]), "r"(b[0]), "r"(b[1]));
}
__device__ __forceinline__ void mma_f16(float* c, const uint32_t* a, const uint32_t* b) {
    asm volatile("mma.sync.aligned.m16n8k16.row.col.f32.f16.f16.f32 "
                 "{%0,%1,%2,%3}, {%4,%5,%6,%7}, {%8,%9}, {%0,%1,%2,%3};"
                 : "+f"(c[0]), "+f"(c[1]), "+f"(c[2]), "+f"(c[3])
                 : "r"(a[0]), "r"(a[1]), "r"(a[2]), "r"(a[3]), "r"(b[0]), "r"(b[1]));
}
__device__ __forceinline__ void bsplit(float x, __nv_bfloat16& h, __nv_bfloat16& l) {
    h = __float2bfloat16(x);
    l = __float2bfloat16(x - __bfloat162float(h));
}
__device__ __forceinline__ void hsplit(float x, __half& h, __half& l) {
    h = __float2half_rn(x);
    l = __float2half_rn(x - __half2float(h));
}
__device__ __forceinline__ __nv_bfloat162 mk2(__nv_bfloat16 a, __nv_bfloat16 b) {
    __nv_bfloat162 v; v.x = a; v.y = b; return v;
}
__device__ __forceinline__ __half2 mkh2(__half a, __half b) {
    __half2 v; v.x = a; v.y = b; return v;
}

// ------------------------- conversion kernels ------------------------------
__global__ __launch_bounds__(256)
void convE_kernel(const float* __restrict__ E) {
    int idx = blockIdx.x * 256 + threadIdx.x;   // over MT*D
    __nv_bfloat16 h, l;
    bsplit(E[idx], h, l);
    g_Eh[idx] = h; g_El[idx] = l;
}

__global__ __launch_bounds__(256)
void convW_kernel(const float* __restrict__ Wk, const float* __restrict__ Wq,
                  const float* __restrict__ Wv) {
    const float* W = (blockIdx.z == 0) ? Wk : (blockIdx.z == 1) ? Wq : Wv;
    const size_t zoff = (size_t)blockIdx.z * D * D;
    __shared__ float tsm[32][33];
    int n0 = blockIdx.x * 32, k0 = blockIdx.y * 32;
    int tx = threadIdx.x, ty = threadIdx.y;
    #pragma unroll
    for (int i = 0; i < 4; i++)
        tsm[ty + 8 * i][tx] = W[(size_t)(k0 + ty + 8 * i) * D + n0 + tx];
    __syncthreads();
    #pragma unroll
    for (int i = 0; i < 4; i++) {
        int n = n0 + ty + 8 * i, k = k0 + tx;
        __nv_bfloat16 h, l;
        bsplit(tsm[tx][ty + 8 * i], h, l);       // = W[k][n]
        g_WTh[zoff + (size_t)n * D + k] = h;     // [n][k]
        g_WTl[zoff + (size_t)n * D + k] = l;
    }
}

// ------------------------- unified mma.sync GEMM ---------------------------
// MODE 0 (qkv): bf16 3-pass split  Al*Bh -> Ah*Bh -> Ah*Bl  (err ~2^-16)
// MODE 1 (scores), MODE 2 (av): fp16 2-pass  Al*Bh -> Ah*Bh  (= A*Bh, err ~2^-12)
//   A = split operand (Q / S), B = single fp16 (K / V).
template <int MODE>
__global__ __launch_bounds__(256, 2)
void gemm_mma(float* __restrict__ outp) {
    __shared__ __align__(128) __nv_bfloat16 sAh[2][2048], sAl[2][2048];
    __shared__ __align__(128) __nv_bfloat16 sBh[2][2304], sBl[2][2304];  // sBl: MODE 0 only

    const int tid = threadIdx.x;
    const int wid = tid >> 5, l = tid & 31;
    const int wm = wid & 1, wn = wid >> 1;          // 2(M) x 4(N) warp grid
    const int warpM = wm * 64, warpN = wn * 32;     // warp tile 64x32
    const int bx = blockIdx.x, by = blockIdx.y, bz = blockIdx.z;
    const int mBase = by * TM, nBase = bx * TN;

    // All staging is bit-agnostic (uint4 / ldsm); only mma interprets the type.
    const __nv_bfloat16 *Agh, *Agl, *Bgh, *Bgl = nullptr;
    int ldkA, nIter;
    if (MODE == 0) {
        Agh = g_Eh; Agl = g_El;
        Bgh = g_WTh + (size_t)bz * D * D; Bgl = g_WTl + (size_t)bz * D * D;
        ldkA = D; nIter = D / BKB;
    } else if (MODE == 1) {
        if (bx > by) return;                        // strictly above diagonal
        Agh = reinterpret_cast<const __nv_bfloat16*>(g_Qh) + (size_t)bz * T * D;
        Agl = reinterpret_cast<const __nv_bfloat16*>(g_Ql) + (size_t)bz * T * D;
        Bgh = reinterpret_cast<const __nv_bfloat16*>(g_Kh) + (size_t)bz * T * D;
        ldkA = D; nIter = D / BKB;
    } else {
        Agh = reinterpret_cast<const __nv_bfloat16*>(g_Sh) + (size_t)bz * T * T;
        Agl = reinterpret_cast<const __nv_bfloat16*>(g_Sl) + (size_t)bz * T * T;
        Bgh = reinterpret_cast<const __nv_bfloat16*>(g_Vh) + (size_t)bz * T * D;
        ldkA = T; nIter = ((by + 1) * TM) / BKB;    // causal K bound
    }

    float c[4][4][4] = {};
    uint4 pt[4];

    // ---- global loader (into registers); one 16B chunk per thread per tile ----
    const int aRow = tid >> 1;
    const int aHalf = tid & 1;
    const int aSts = pOff(aRow, aHalf);        // plane-split STS offset (bytes)
    const int vRow = tid >> 4;                 // mode2 B tile rows
    const int vNc  = (tid & 15) * 8;

    auto loadG = [&](int ko) {
        const size_t aoff = (size_t)(mBase + aRow) * ldkA + ko + aHalf * 8;
        pt[0] = *(const uint4*)(Agh + aoff);
        pt[1] = *(const uint4*)(Agl + aoff);
        if (MODE != 2) {
            const size_t boff = (size_t)(nBase + aRow) * D + ko + aHalf * 8;
            pt[2] = *(const uint4*)(Bgh + boff);
            if (MODE == 0) pt[3] = *(const uint4*)(Bgl + boff);
        } else {
            const size_t boff = (size_t)(ko + vRow) * D + nBase + vNc;
            pt[2] = *(const uint4*)(Bgh + boff);
        }
    };
    auto stsAll = [&](int buf) {
        *(uint4*)((char*)sAh[buf] + aSts) = pt[0];
        *(uint4*)((char*)sAl[buf] + aSts) = pt[1];
        if (MODE != 2) {
            *(uint4*)((char*)sBh[buf] + aSts) = pt[2];
            if (MODE == 0) *(uint4*)((char*)sBl[buf] + aSts) = pt[3];
        } else {
            *(uint4*)&sBh[buf][vRow * B2STR + vNc] = pt[2];
        }
    };

    // lane-invariant ldsm addressing pieces (plane-split layout)
    const int aPl = l >> 4;                         // A: plane select
    const int aRw = ((l >> 3) & 1) * 8 + (l & 7);   // A: row within 16-group
    const int bPl = (l >> 3) & 1;                   // B: plane select
    const int bRw = (l & 7) + (l >> 4) * 8;         // B: row within 16-group
    // mode2 trans ldsm pieces (padded [k][n] layout)
    const int vLR = ((l >> 3) & 1) * 8 + (l & 7), vLC = (l >> 4) * 8;

    auto ldsmA = [&](uint32_t (&a)[4][4], const __nv_bfloat16* base) {
        const uint32_t u = smem_u32(base);
        #pragma unroll
        for (int mi = 0; mi < 4; mi++)
            ldsm_x4(a[mi][0], a[mi][1], a[mi][2], a[mi][3],
                    u + pOff(warpM + mi * 16 + aRw, aPl));
    };
    auto ldsmB = [&](uint32_t (&b)[4][2], const __nv_bfloat16* base) {
        const uint32_t u = smem_u32(base);
        if (MODE != 2) {
            #pragma unroll
            for (int n2 = 0; n2 < 4; n2 += 2)
                ldsm_x4(b[n2][0], b[n2][1], b[n2 + 1][0], b[n2 + 1][1],
                        u + pOff(warpN + n2 * 8 + bRw, bPl));
        } else {
            #pragma unroll
            for (int n2 = 0; n2 < 4; n2 += 2)
                ldsm_x4_t(b[n2][0], b[n2][1], b[n2 + 1][0], b[n2 + 1][1],
                          u + (vLR * B2STR + warpN + n2 * 8 + vLC) * 2);
        }
    };
    auto mmaAll = [&](uint32_t (&a)[4][4], uint32_t (&b)[4][2]) {
        #pragma unroll
        for (int mi = 0; mi < 4; mi++)
            #pragma unroll
            for (int ni = 0; ni < 4; ni++) {
                if (MODE == 0) mma_bf16(c[mi][ni], a[mi], b[ni]);
                else           mma_f16(c[mi][ni], a[mi], b[ni]);
            }
    };

    // ---- prologue: fill buffer 0 ----
    loadG(0);
    stsAll(0);
    __syncthreads();

    // ---- main loop: one barrier per iter, chained passes, STS at end ----
    for (int it = 0; it < nIter; it++) {
        const int buf = it & 1;
        const bool more = (it + 1 < nIter);
        if (more) loadG((it + 1) * BKB);   // LDG latency rides under the MMAs

        uint32_t a[4][4], b[4][2];
        ldsmA(a, sAl[buf]);
        ldsmB(b, sBh[buf]);
        mmaAll(a, b);                      // Al * Bh
        ldsmA(a, sAh[buf]);
        mmaAll(a, b);                      // Ah * Bh   (b held in regs)
        if (MODE == 0) {
            ldsmB(b, sBl[buf]);
            mmaAll(a, b);                  // Ah * Bl   (a held in regs)
        }

        if (more) {
            stsAll(buf ^ 1);               // other buffer; safe before barrier
            __syncthreads();               // single barrier per iteration
        }
    }

    // ---- epilogue (direct from accumulators) ----
    const int l4 = l >> 2, l2 = (l & 3) * 2;
    #pragma unroll
    for (int mi = 0; mi < 4; mi++) {
        #pragma unroll
        for (int ni = 0; ni < 4; ni++) {
            const int n = nBase + warpN + ni * 8 + l2;
            #pragma unroll
            for (int half = 0; half < 2; half++) {
                const int m = mBase + warpM + mi * 16 + l4 + half * 8;
                float v0 = c[mi][ni][half * 2 + 0];
                float v1 = c[mi][ni][half * 2 + 1];
                if (MODE == 0) {
                    const size_t off = (size_t)m * D + n;
                    if (bz == 1) {          // Q: fp16 split pair
                        __half h0, l0, h1, l1;
                        hsplit(v0, h0, l0); hsplit(v1, h1, l1);
                        *(__half2*)(g_Qh + off) = mkh2(h0, h1);
                        *(__half2*)(g_Ql + off) = mkh2(l0, l1);
                    } else if (bz == 0) {   // K: single fp16
                        *(__half2*)(g_Kh + off) =
                            mkh2(__float2half_rn(v0), __float2half_rn(v1));
                    } else {                // V: single fp16, [b][t][d]
                        *(__half2*)(g_Vh + off) =
                            mkh2(__float2half_rn(v0), __float2half_rn(v1));
                    }
                } else if (MODE == 1) {
                    float s0 = (n     > m) ? -INFINITY : v0 * 0.03125f;
                    float s1 = (n + 1 > m) ? -INFINITY : v1 * 0.03125f;
                    float* p = g_S + (size_t)bz * T * T + (size_t)m * T + n;
                    p[0] = s0; p[1] = s1;
                } else {
                    float* p = outp + (size_t)bz * T * D + (size_t)m * D + n;
                    p[0] = rintf(v0 * 10000.0f) * 1.0e-4f;
                    p[1] = rintf(v1 * 10000.0f) * 1.0e-4f;
                }
            }
        }
    }
}

// ------------------------- softmax (warp per row) -> split fp16 ------------
__global__ __launch_bounds__(256)
void softmax_kernel() {
    const int wid = threadIdx.x >> 5, l = threadIdx.x & 31;
    const int r = blockIdx.x * 8 + wid;
    const int b = r >> 11, t = r & (T - 1);
    float* row = g_S + (size_t)b * T * T + (size_t)t * T;
    __half* oh = g_Sh + ((size_t)b * T + t) * T;
    __half* ol = g_Sl + ((size_t)b * T + t) * T;
    const int L = ((t >> 7) + 1) << 7;   // ceil to 128-tile

    float m = -INFINITY;
    for (int j = l; j < L; j += 32) m = fmaxf(m, row[j]);
    #pragma unroll
    for (int off = 16; off > 0; off >>= 1)
        m = fmaxf(m, __shfl_xor_sync(0xFFFFFFFFu, m, off));

    float sum = 0.0f;
    for (int j = l; j < L; j += 32) {
        float e = __expf(row[j] - m);   // exp(-inf)=0 handles the causal mask
        row[j] = e;
        sum += e;
    }
    #pragma unroll
    for (int off = 16; off > 0; off >>= 1)
        sum += __shfl_xor_sync(0xFFFFFFFFu, sum, off);
    const float inv = 1.0f / sum;

    for (int j = l; j < L; j += 32) {
        float w = row[j] * inv;
        __half h, ll;
        hsplit(w, h, ll);
        oh[j] = h; ol[j] = ll;
    }
}

// ---------------------------------------------------------------------------
extern "C" void kernel_launch(void* const* d_in, const int* in_sizes, int n_in,
                              void* d_out, int out_size) {
    const float* E  = (const float*)d_in[0];
    const float* Wk = (const float*)d_in[1];
    const float* Wq = (const float*)d_in[2];
    const float* Wv = (const float*)d_in[3];
    float* O = (float*)d_out;

    convE_kernel<<<(MT * D) / 256, 256>>>(E);
    convW_kernel<<<dim3(32, 32, 3), dim3(32, 8)>>>(Wk, Wq, Wv);
    gemm_mma<0><<<dim3(D / TN, MT / TM, 3), 256>>>(O);
    gemm_mma<1><<<dim3(T / TN, T / TM, BATCH), 256>>>(O);
    softmax_kernel<<<MT / 8, 256>>>();
    gemm_mma<2><<<dim3(D / TN, T / TM, BATCH), 256>>>(O);
}

// round 16
// speedup vs baseline: 1.2860x; 1.0650x over previous
#include <cuda_runtime.h>
#include <cuda_bf16.h>
#include <cuda_fp16.h>
#include <stdint.h>
#include <stddef.h>
#include <math.h>

#define BATCH 4
#define T     2048
#define D     1024
#define MT    (BATCH * T)   // 8192

// CTA tile 128x128, 8 warps (2M x 4N), warp tile 64x32, base-K chunk = 16
#define TM 128
#define TN 128
#define BKB 16
// A/B (mode!=2) tiles: plane-split layout, 2 planes x 128 rows x 16B, plane1
// rotated by 64B -> conflict-free STS.128 AND conflict-free ldsm. 4096B/tile.
#define B2STR 136    // mode2 V tiles: 128+8 pad elems (272B rows), conflict-free

// ------------------------- device scratch (all fp16 hi/lo) -----------------
__device__ __half g_Eh[(size_t)MT * D],  g_El[(size_t)MT * D];
__device__ __half g_WTh[(size_t)3 * D * D], g_WTl[(size_t)3 * D * D]; // [z][n][k]
__device__ __half g_Qh[(size_t)MT * D], g_Ql[(size_t)MT * D];
__device__ __half g_Kh[(size_t)MT * D];
__device__ __half g_Vh[(size_t)MT * D];                     // [b][t][d]
__device__ float  g_S[(size_t)BATCH * T * T];               // fp32 scores
__device__ __half g_Sh[(size_t)BATCH * T * T], g_Sl[(size_t)BATCH * T * T];

// ------------------------- helpers ------------------------------------
__device__ __forceinline__ uint32_t smem_u32(const void* p) {
    uint32_t a;
    asm("{ .reg .u64 t; cvta.to.shared.u64 t, %1; cvt.u32.u64 %0, t; }" : "=r"(a) : "l"(p));
    return a;
}
// byte offset of (row, k-half) 16B chunk inside a plane-split tile
__device__ __forceinline__ int pOff(int row, int half) {
    return half * 2048 + (((row << 4) + (half << 6)) & 2047);
}
__device__ __forceinline__ void ldsm_x4(uint32_t& r0, uint32_t& r1, uint32_t& r2, uint32_t& r3,
                                        uint32_t addr) {
    asm volatile("ldmatrix.sync.aligned.m8n8.x4.shared.b16 {%0,%1,%2,%3}, [%4];"
                 : "=r"(r0), "=r"(r1), "=r"(r2), "=r"(r3) : "r"(addr));
}
__device__ __forceinline__ void ldsm_x4_t(uint32_t& r0, uint32_t& r1, uint32_t& r2, uint32_t& r3,
                                          uint32_t addr) {
    asm volatile("ldmatrix.sync.aligned.m8n8.x4.trans.shared.b16 {%0,%1,%2,%3}, [%4];"
                 : "=r"(r0), "=r"(r1), "=r"(r2), "=r"(r3) : "r"(addr));
}
__device__ __forceinline__ void mma_f16(float* c, const uint32_t* a, const uint32_t* b) {
    asm volatile("mma.sync.aligned.m16n8k16.row.col.f32.f16.f16.f32 "
                 "{%0,%1,%2,%3}, {%4,%5,%6,%7}, {%8,%9}, {%0,%1,%2,%3};"
                 : "+f"(c[0]), "+f"(c[1]), "+f"(c[2]), "+f"(c[3])
                 : "r"(a[0]), "r"(a[1]), "r"(a[2]), "r"(a[3]), "r"(b[0]), "r"(b[1]));
}
__device__ __forceinline__ void hsplit(float x, __half& h, __half& l) {
    h = __float2half_rn(x);
    l = __float2half_rn(x - __half2float(h));
}
__device__ __forceinline__ __half2 mkh2(__half a, __half b) {
    __half2 v; v.x = a; v.y = b; return v;
}

// ------------------------- conversion kernels ------------------------------
__global__ __launch_bounds__(256)
void convE_kernel(const float* __restrict__ E) {
    int idx = blockIdx.x * 256 + threadIdx.x;   // over MT*D
    __half h, l;
    hsplit(E[idx], h, l);
    g_Eh[idx] = h; g_El[idx] = l;
}

__global__ __launch_bounds__(256)
void convW_kernel(const float* __restrict__ Wk, const float* __restrict__ Wq,
                  const float* __restrict__ Wv) {
    const float* W = (blockIdx.z == 0) ? Wk : (blockIdx.z == 1) ? Wq : Wv;
    const size_t zoff = (size_t)blockIdx.z * D * D;
    __shared__ float tsm[32][33];
    int n0 = blockIdx.x * 32, k0 = blockIdx.y * 32;
    int tx = threadIdx.x, ty = threadIdx.y;
    #pragma unroll
    for (int i = 0; i < 4; i++)
        tsm[ty + 8 * i][tx] = W[(size_t)(k0 + ty + 8 * i) * D + n0 + tx];
    __syncthreads();
    #pragma unroll
    for (int i = 0; i < 4; i++) {
        int n = n0 + ty + 8 * i, k = k0 + tx;
        __half h, l;
        hsplit(tsm[tx][ty + 8 * i], h, l);       // = W[k][n]
        g_WTh[zoff + (size_t)n * D + k] = h;     // [n][k]
        g_WTl[zoff + (size_t)n * D + k] = l;
    }
}

// ------------------------- unified mma.sync GEMM (all fp16) ----------------
// MODE 0 (qkv): z=V (bz==2): 3-pass  Al*Bh -> Ah*Bh -> Ah*Bl   (err ~2^-22)
//               z=K,Q:       2-pass  Al*Bh -> Ah*Bh (= E*Wh)   (err ~2^-12,
//               damped to ~1e-4 on the output by the 1/32 scale + softmax)
// MODE 1 (scores), MODE 2 (av): fp16 2-pass (A split, B single).
template <int MODE>
__global__ __launch_bounds__(256, 2)
void gemm_mma(float* __restrict__ outp) {
    __shared__ __align__(128) __half sAh[2][2048], sAl[2][2048];
    __shared__ __align__(128) __half sBh[2][2304], sBl[2][2304];  // sBl: MODE0 z=V only

    const int tid = threadIdx.x;
    const int wid = tid >> 5, l = tid & 31;
    const int wm = wid & 1, wn = wid >> 1;          // 2(M) x 4(N) warp grid
    const int warpM = wm * 64, warpN = wn * 32;     // warp tile 64x32
    const int bx = blockIdx.x, by = blockIdx.y, bz = blockIdx.z;
    const int mBase = by * TM, nBase = bx * TN;

    const __half *Agh, *Agl, *Bgh, *Bgl = nullptr;
    int ldkA, nIter;
    bool needBl = false;
    if (MODE == 0) {
        Agh = g_Eh; Agl = g_El;
        Bgh = g_WTh + (size_t)bz * D * D; Bgl = g_WTl + (size_t)bz * D * D;
        ldkA = D; nIter = D / BKB;
        needBl = (bz == 2);                         // V needs the 3rd pass
    } else if (MODE == 1) {
        if (bx > by) return;                        // strictly above diagonal
        Agh = g_Qh + (size_t)bz * T * D; Agl = g_Ql + (size_t)bz * T * D;
        Bgh = g_Kh + (size_t)bz * T * D;
        ldkA = D; nIter = D / BKB;
    } else {
        Agh = g_Sh + (size_t)bz * T * T; Agl = g_Sl + (size_t)bz * T * T;
        Bgh = g_Vh + (size_t)bz * T * D;
        ldkA = T; nIter = ((by + 1) * TM) / BKB;    // causal K bound
    }

    float c[4][4][4] = {};
    uint4 pt[4];

    // ---- global loader (into registers); one 16B chunk per thread per tile ----
    const int aRow = tid >> 1;
    const int aHalf = tid & 1;
    const int aSts = pOff(aRow, aHalf);        // plane-split STS offset (bytes)
    const int vRow = tid >> 4;                 // mode2 B tile rows
    const int vNc  = (tid & 15) * 8;

    auto loadG = [&](int ko) {
        const size_t aoff = (size_t)(mBase + aRow) * ldkA + ko + aHalf * 8;
        pt[0] = *(const uint4*)(Agh + aoff);
        pt[1] = *(const uint4*)(Agl + aoff);
        if (MODE != 2) {
            const size_t boff = (size_t)(nBase + aRow) * D + ko + aHalf * 8;
            pt[2] = *(const uint4*)(Bgh + boff);
            if (MODE == 0 && needBl) pt[3] = *(const uint4*)(Bgl + boff);
        } else {
            const size_t boff = (size_t)(ko + vRow) * D + nBase + vNc;
            pt[2] = *(const uint4*)(Bgh + boff);
        }
    };
    auto stsAll = [&](int buf) {
        *(uint4*)((char*)sAh[buf] + aSts) = pt[0];
        *(uint4*)((char*)sAl[buf] + aSts) = pt[1];
        if (MODE != 2) {
            *(uint4*)((char*)sBh[buf] + aSts) = pt[2];
            if (MODE == 0 && needBl) *(uint4*)((char*)sBl[buf] + aSts) = pt[3];
        } else {
            *(uint4*)&sBh[buf][vRow * B2STR + vNc] = pt[2];
        }
    };

    // lane-invariant ldsm addressing pieces (plane-split layout)
    const int aPl = l >> 4;                         // A: plane select
    const int aRw = ((l >> 3) & 1) * 8 + (l & 7);   // A: row within 16-group
    const int bPl = (l >> 3) & 1;                   // B: plane select
    const int bRw = (l & 7) + (l >> 4) * 8;         // B: row within 16-group
    // mode2 trans ldsm pieces (padded [k][n] layout)
    const int vLR = ((l >> 3) & 1) * 8 + (l & 7), vLC = (l >> 4) * 8;

    auto ldsmA = [&](uint32_t (&a)[4][4], const __half* base) {
        const uint32_t u = smem_u32(base);
        #pragma unroll
        for (int mi = 0; mi < 4; mi++)
            ldsm_x4(a[mi][0], a[mi][1], a[mi][2], a[mi][3],
                    u + pOff(warpM + mi * 16 + aRw, aPl));
    };
    auto ldsmB = [&](uint32_t (&b)[4][2], const __half* base) {
        const uint32_t u = smem_u32(base);
        if (MODE != 2) {
            #pragma unroll
            for (int n2 = 0; n2 < 4; n2 += 2)
                ldsm_x4(b[n2][0], b[n2][1], b[n2 + 1][0], b[n2 + 1][1],
                        u + pOff(warpN + n2 * 8 + bRw, bPl));
        } else {
            #pragma unroll
            for (int n2 = 0; n2 < 4; n2 += 2)
                ldsm_x4_t(b[n2][0], b[n2][1], b[n2 + 1][0], b[n2 + 1][1],
                          u + (vLR * B2STR + warpN + n2 * 8 + vLC) * 2);
        }
    };
    auto mmaAll = [&](uint32_t (&a)[4][4], uint32_t (&b)[4][2]) {
        #pragma unroll
        for (int mi = 0; mi < 4; mi++)
            #pragma unroll
            for (int ni = 0; ni < 4; ni++)
                mma_f16(c[mi][ni], a[mi], b[ni]);
    };

    // ---- prologue: fill buffer 0 ----
    loadG(0);
    stsAll(0);
    __syncthreads();

    // ---- main loop: one barrier per iter, chained passes, STS at end ----
    for (int it = 0; it < nIter; it++) {
        const int buf = it & 1;
        const bool more = (it + 1 < nIter);
        if (more) loadG((it + 1) * BKB);   // LDG latency rides under the MMAs

        uint32_t a[4][4], b[4][2];
        ldsmA(a, sAl[buf]);
        ldsmB(b, sBh[buf]);
        mmaAll(a, b);                      // Al * Bh
        ldsmA(a, sAh[buf]);
        mmaAll(a, b);                      // Ah * Bh   (b held in regs)
        if (MODE == 0 && needBl) {
            ldsmB(b, sBl[buf]);
            mmaAll(a, b);                  // Ah * Bl   (a held in regs)
        }

        if (more) {
            stsAll(buf ^ 1);               // other buffer; safe before barrier
            __syncthreads();               // single barrier per iteration
        }
    }

    // ---- epilogue (direct from accumulators) ----
    const int l4 = l >> 2, l2 = (l & 3) * 2;
    #pragma unroll
    for (int mi = 0; mi < 4; mi++) {
        #pragma unroll
        for (int ni = 0; ni < 4; ni++) {
            const int n = nBase + warpN + ni * 8 + l2;
            #pragma unroll
            for (int half = 0; half < 2; half++) {
                const int m = mBase + warpM + mi * 16 + l4 + half * 8;
                float v0 = c[mi][ni][half * 2 + 0];
                float v1 = c[mi][ni][half * 2 + 1];
                if (MODE == 0) {
                    const size_t off = (size_t)m * D + n;
                    if (bz == 1) {          // Q: fp16 split pair
                        __half h0, l0, h1, l1;
                        hsplit(v0, h0, l0); hsplit(v1, h1, l1);
                        *(__half2*)(g_Qh + off) = mkh2(h0, h1);
                        *(__half2*)(g_Ql + off) = mkh2(l0, l1);
                    } else if (bz == 0) {   // K: single fp16
                        *(__half2*)(g_Kh + off) =
                            mkh2(__float2half_rn(v0), __float2half_rn(v1));
                    } else {                // V: single fp16, [b][t][d]
                        *(__half2*)(g_Vh + off) =
                            mkh2(__float2half_rn(v0), __float2half_rn(v1));
                    }
                } else if (MODE == 1) {
                    float s0 = (n     > m) ? -INFINITY : v0 * 0.03125f;
                    float s1 = (n + 1 > m) ? -INFINITY : v1 * 0.03125f;
                    float* p = g_S + (size_t)bz * T * T + (size_t)m * T + n;
                    p[0] = s0; p[1] = s1;
                } else {
                    float* p = outp + (size_t)bz * T * D + (size_t)m * D + n;
                    p[0] = rintf(v0 * 10000.0f) * 1.0e-4f;
                    p[1] = rintf(v1 * 10000.0f) * 1.0e-4f;
                }
            }
        }
    }
}

// ------------------------- softmax (warp per row) -> split fp16 ------------
__global__ __launch_bounds__(256)
void softmax_kernel() {
    const int wid = threadIdx.x >> 5, l = threadIdx.x & 31;
    const int r = blockIdx.x * 8 + wid;
    const int b = r >> 11, t = r & (T - 1);
    float* row = g_S + (size_t)b * T * T + (size_t)t * T;
    __half* oh = g_Sh + ((size_t)b * T + t) * T;
    __half* ol = g_Sl + ((size_t)b * T + t) * T;
    const int L = ((t >> 7) + 1) << 7;   // ceil to 128-tile

    float m = -INFINITY;
    for (int j = l; j < L; j += 32) m = fmaxf(m, row[j]);
    #pragma unroll
    for (int off = 16; off > 0; off >>= 1)
        m = fmaxf(m, __shfl_xor_sync(0xFFFFFFFFu, m, off));

    float sum = 0.0f;
    for (int j = l; j < L; j += 32) {
        float e = __expf(row[j] - m);   // exp(-inf)=0 handles the causal mask
        row[j] = e;
        sum += e;
    }
    #pragma unroll
    for (int off = 16; off > 0; off >>= 1)
        sum += __shfl_xor_sync(0xFFFFFFFFu, sum, off);
    const float inv = 1.0f / sum;

    for (int j = l; j < L; j += 32) {
        float w = row[j] * inv;
        __half h, ll;
        hsplit(w, h, ll);
        oh[j] = h; ol[j] = ll;
    }
}

// ---------------------------------------------------------------------------
extern "C" void kernel_launch(void* const* d_in, const int* in_sizes, int n_in,
                              void* d_out, int out_size) {
    const float* E  = (const float*)d_in[0];
    const float* Wk = (const float*)d_in[1];
    const float* Wq = (const float*)d_in[2];
    const float* Wv = (const float*)d_in[3];
    float* O = (float*)d_out;

    convE_kernel<<<(MT * D) / 256, 256>>>(E);
    convW_kernel<<<dim3(32, 32, 3), dim3(32, 8)>>>(Wk, Wq, Wv);
    gemm_mma<0><<<dim3(D / TN, MT / TM, 3), 256>>>(O);
    gemm_mma<1><<<dim3(T / TN, T / TM, BATCH), 256>>>(O);
    softmax_kernel<<<MT / 8, 256>>>();
    gemm_mma<2><<<dim3(D / TN, T / TM, BATCH), 256>>>(O);
}